// round 16
// baseline (speedup 1.0000x reference)
#include <cuda_runtime.h>

#define THREADS 256
#define TB 16
// smem: wp [m][n][4] 64KB + wm 64KB + 2 x-buffers of 32KB = 192KB
#define SMEM_BYTES 196608

typedef unsigned long long ull;

__device__ __forceinline__ ull pk2(float lo, float hi) {
    ull r;
    asm("mov.b64 %0, {%1, %2};" : "=l"(r) : "f"(lo), "f"(hi));
    return r;
}
__device__ __forceinline__ void unpk(ull v, float& lo, float& hi) {
    asm("mov.b64 {%0, %1}, %2;" : "=f"(lo), "=f"(hi) : "l"(v));
}
__device__ __forceinline__ ull ffma2(ull a, ull b, ull c) {
    ull d;
    asm("fma.rn.f32x2 %0, %1, %2, %3;" : "=l"(d) : "l"(a), "l"(b), "l"(c));
    return d;
}

// ---------------------------------------------------------------------------
// stage one tile (TB=16 batches = 32KB) into smem as [m][j][chunk][v]:
//   element (b, m, chunk) -> m*512 + (b>>2)*128 + chunk*64 + (b&3)*16
// Reader thread (v = lane>>3) load (j, chunk):
//   xt + m*512 + j*128 + chunk*64 + v*16  -> 4 variants x 16B = 64B in one
//   128B line -> 1 wavefront, broadcast across the 8 n-duplicates.
// ---------------------------------------------------------------------------
__device__ __forceinline__ void stage_tile(const float* __restrict__ x,
                                           char* dstbase, int tile, int tid) {
    const float4* src = reinterpret_cast<const float4*>(x) + (size_t)tile * 2048;
    unsigned int dsb = (unsigned int)__cvta_generic_to_shared(dstbase);
#pragma unroll
    for (int k = 0; k < 8; k++) {
        int i = tid + k * THREADS;
        int b = i >> 7, mh = i & 127, m = mh >> 1, c = mh & 1;
        unsigned int db = (unsigned)(m * 512 + ((b >> 2) << 7) + (c << 6)
                                     + ((b & 3) << 4));
        asm volatile("cp.async.cg.shared.global [%0], [%1], 16;\n"
                     :: "r"(dsb + db), "l"(src + i));
    }
    asm volatile("cp.async.commit_group;\n");
}

// ---- pipeline stage helpers (keep loads / math separable for ptxas) ----
__device__ __forceinline__ void ldw(const float4* __restrict__ wsp,
                                    const float4* __restrict__ wsm,
                                    int m, int n, float4& wpv, float4& wmv) {
    wpv = wsp[(m << 6) + n];
    wmv = wsm[(m << 6) + n];
}

__device__ __forceinline__ void ldx(const char* __restrict__ xt, int m,
                                    ulonglong2* c0, ulonglong2* c1) {
    const char* xm = xt + m * 512;
#pragma unroll
    for (int j = 0; j < 4; j++) {
        c0[j] = *reinterpret_cast<const ulonglong2*>(xm + (j << 7));
        c1[j] = *reinterpret_cast<const ulonglong2*>(xm + (j << 7) + 64);
    }
}

// one m-step of both GEMMs: per-blade single-accumulator fused-fma chains,
// m ascending — DO NOT change (bit-exact vs reference; gate/q are singular).
__device__ __forceinline__ void domma(const float4& wpv, const float4& wmv,
                                      const ulonglong2* c0, const ulonglong2* c1,
                                      ull aP[4][4], ull aM[4][4]) {
    // SUBSPACE packs: A=(w0,w1), B=(w1,w1), C=(w2,w2), D=(w2,w3)
    ull wpA, wpD, wmA, wmD;
    {
        const ulonglong2* u = reinterpret_cast<const ulonglong2*>(&wpv);
        wpA = u->x; wpD = u->y;
        const ulonglong2* v = reinterpret_cast<const ulonglong2*>(&wmv);
        wmA = v->x; wmD = v->y;
    }
    ull wpB = pk2(wpv.y, wpv.y), wpC = pk2(wpv.z, wpv.z);
    ull wmB = pk2(wmv.y, wmv.y), wmC = pk2(wmv.z, wmv.z);
#pragma unroll
    for (int j = 0; j < 4; j++) {
        aP[j][0] = ffma2(c0[j].x, wpA, aP[j][0]);   // blades 0,1
        aP[j][1] = ffma2(c0[j].y, wpB, aP[j][1]);   // blades 2,3
        aP[j][2] = ffma2(c1[j].x, wpC, aP[j][2]);   // blades 4,5
        aP[j][3] = ffma2(c1[j].y, wpD, aP[j][3]);   // blades 6,7
        aM[j][0] = ffma2(c0[j].x, wmA, aM[j][0]);
        aM[j][1] = ffma2(c0[j].y, wmB, aM[j][1]);
        aM[j][2] = ffma2(c1[j].x, wmC, aM[j][2]);
        aM[j][3] = ffma2(c1[j].y, wmD, aM[j][3]);
    }
}

__global__ __launch_bounds__(THREADS, 1)
void clifford_gate_kernel(const float* __restrict__ x,
                          const float* __restrict__ wp,
                          const float* __restrict__ bpr,
                          const float* __restrict__ wm,
                          const float* __restrict__ bmr,
                          float* __restrict__ out,
                          int ntiles) {
    extern __shared__ char smc[];
    float4* wsp = reinterpret_cast<float4*>(smc);          // 4096 float4, [m*64+n]
    float4* wsm = wsp + 4096;                               // 4096 float4
    char*   xb  = smc + 131072;                             // 2 x 32KB tiles

    const int tid  = threadIdx.x;
    const int lane = tid & 31;
    const int warp = tid >> 5;
    const int n = (warp << 3) | (lane & 7);   // 8 warps x 8 n = 64 n
    const int v = lane >> 3;                  // variant 0..3; b = 4j + v

    // ---- stage weights once: gmem [n][m][4] -> smem [m][n][4] ----
    {
        const float4* gp = reinterpret_cast<const float4*>(wp);
        const float4* gm = reinterpret_cast<const float4*>(wm);
        for (int idx = tid; idx < 4096; idx += THREADS) {
            int nn = idx & 63, mm = idx >> 6;
            wsp[mm * 64 + nn] = gp[nn * 64 + mm];
            wsm[mm * 64 + nn] = gm[nn * 64 + mm];
        }
    }
    const float biasp = bpr[n];
    const float biasm = bmr[n];

    int t = blockIdx.x;
    const int stride = gridDim.x;
    if (t < ntiles) stage_tile(x, xb, t, tid);
    asm volatile("cp.async.wait_group 0;\n");
    __syncthreads();

    int cur = 0;
    const float s2 = 0.70710678118654752440f;
    const int voff = v << 4;

    for (; t < ntiles; t += stride) {
        int tn = t + stride;
        if (tn < ntiles) stage_tile(x, xb + (cur ^ 1) * 32768, tn, tid);

        ull aP[4][4], aM[4][4];
#pragma unroll
        for (int i = 0; i < 4; i++)
#pragma unroll
            for (int j = 0; j < 4; j++) { aP[i][j] = 0ull; aM[i][j] = 0ull; }

        const char* xt = xb + cur * 32768 + voff;

        // ---- software-pipelined mainloop: prefetch depth 1 m, ping-pong ----
        float4 wpA4, wmA4, wpB4, wmB4;
        ulonglong2 a0[4], a1[4], b0[4], b1[4];

        ldw(wsp, wsm, 0, n, wpA4, wmA4);
        ldx(xt, 0, a0, a1);

#pragma unroll 4
        for (int m = 0; m < 64; m += 2) {
            // prefetch m+1 into set B, then consume set A (m)
            ldw(wsp, wsm, m + 1, n, wpB4, wmB4);
            ldx(xt, m + 1, b0, b1);
            domma(wpA4, wmA4, a0, a1, aP, aM);
            // prefetch m+2 (wraps to 0 on last block; loaded value unused)
            int m2 = (m + 2) & 63;
            ldw(wsp, wsm, m2, n, wpA4, wmA4);
            ldx(xt, m2, a0, a1);
            domma(wpB4, wmB4, b0, b1, aP, aM);
        }

        // ---------------- epilogue ----------------
#pragma unroll
        for (int j = 0; j < 4; j++) {
            float p0, p1, p2, p3, p4, p5, p6, p7;
            float m0, m1, m2, m3, m4, m5, m6, m7;
            unpk(aP[j][0], p0, p1); unpk(aP[j][1], p2, p3);
            unpk(aP[j][2], p4, p5); unpk(aP[j][3], p6, p7);
            unpk(aM[j][0], m0, m1); unpk(aM[j][1], m2, m3);
            unpk(aM[j][2], m4, m5); unpk(aM[j][3], m6, m7);
            p0 = __fadd_rn(p0, biasp);
            m0 = __fadd_rn(m0, biasm);

            // gate: individually rounded multiplies + sequential adds i=0..7.
            // NO FMA here (bit-exactness near b==0 is required).
            float bgv;
            bgv = __fmul_rn(p0, m0);
            bgv = __fadd_rn(bgv, __fmul_rn(p1, m1));
            bgv = __fadd_rn(bgv, __fmul_rn(p2, m2));
            bgv = __fadd_rn(bgv, __fmul_rn(p3, m3));
            bgv = __fadd_rn(bgv, __fmul_rn(p4, m4));
            bgv = __fadd_rn(bgv, __fmul_rn(p5, m5));
            bgv = __fadd_rn(bgv, __fmul_rn(p6, m6));
            bgv = __fadd_rn(bgv, __fmul_rn(p7, m7));

            // q: same rounding discipline (singular near q==0).
            float qv;
            qv = __fmul_rn(m0, m0);
            qv = __fadd_rn(qv, __fmul_rn(m1, m1));
            qv = __fadd_rn(qv, __fmul_rn(m2, m2));
            qv = __fadd_rn(qv, __fmul_rn(m3, m3));
            qv = __fadd_rn(qv, -__fmul_rn(m4, m4));
            qv = __fadd_rn(qv, -__fmul_rn(m5, m5));
            qv = __fadd_rn(qv, -__fmul_rn(m6, m6));
            qv = __fadd_rn(qv, -__fmul_rn(m7, m7));

            float qs  = __fadd_rn(__fmul_rn(qv, qv), 1e-16f);
            float nrm = __fsqrt_rn(__fsqrt_rn(qs));
            float inv = __frcp_rn(nrm);

            float n0 = m0 * inv, n1 = m1 * inv, n2 = m2 * inv, n3 = m3 * inv;
            float n4 = m4 * inv, n5 = m5 * inv, n6 = m6 * inv, n7 = m7 * inv;

            // Cl(3,0) geometric product r = p * n (well-conditioned; fma ok)
            float r0 = p0*n0 + p1*n1 + p2*n2 + p3*n3 - p4*n4 - p5*n5 - p6*n6 - p7*n7;
            float r1 = p0*n1 + p1*n0 - p2*n4 + p4*n2 - p3*n5 + p5*n3 - p6*n7 - p7*n6;
            float r2 = p0*n2 + p2*n0 + p1*n4 - p4*n1 - p3*n6 + p6*n3 + p5*n7 + p7*n5;
            float r3 = p0*n3 + p3*n0 + p1*n5 - p5*n1 + p2*n6 - p6*n2 - p4*n7 - p7*n4;
            float r4 = p0*n4 + p4*n0 + p1*n2 - p2*n1 + p3*n7 + p7*n3 - p5*n6 + p6*n5;
            float r5 = p0*n5 + p5*n0 + p1*n3 - p3*n1 - p2*n7 - p7*n2 + p4*n6 - p6*n4;
            float r6 = p0*n6 + p6*n0 + p1*n7 + p7*n1 + p2*n3 - p3*n2 - p4*n5 + p5*n4;
            float r7 = p0*n7 + p7*n0 + p1*n6 + p6*n1 - p2*n5 - p5*n2 + p3*n4 + p4*n3;

            bool sel = bgv > 0.0f;
            float4 o0, o1;
            o0.x = (sel ? p0 : r0) * s2;
            o0.y = (sel ? p1 : r1) * s2;
            o0.z = (sel ? p2 : r2) * s2;
            o0.w = (sel ? p3 : r3) * s2;
            o1.x = (sel ? p4 : r4) * s2;
            o1.y = (sel ? p5 : r5) * s2;
            o1.z = (sel ? p6 : r6) * s2;
            o1.w = (sel ? p7 : r7) * s2;

            size_t brow = (size_t)t * TB + (size_t)(4 * j + v);
            float4* op = reinterpret_cast<float4*>(out + ((brow << 6) + n) * 8);
            op[0] = o0;
            op[1] = o1;
        }

        asm volatile("cp.async.wait_group 0;\n");
        __syncthreads();
        cur ^= 1;
    }
}

extern "C" void kernel_launch(void* const* d_in, const int* in_sizes, int n_in,
                              void* d_out, int out_size) {
    const float* x   = (const float*)d_in[0];
    const float* wp  = (const float*)d_in[1];
    const float* bpr = (const float*)d_in[2];
    const float* wm  = (const float*)d_in[3];
    const float* bmr = (const float*)d_in[4];
    float* out = (float*)d_out;

    int B = in_sizes[0] / 512;      // x is (B, 64, 8)
    int ntiles = B / TB;

    cudaFuncSetAttribute(clifford_gate_kernel,
                         cudaFuncAttributeMaxDynamicSharedMemorySize, SMEM_BYTES);

    int dev = 0, sms = 148;
    cudaGetDevice(&dev);
    cudaDeviceGetAttribute(&sms, cudaDevAttrMultiProcessorCount, dev);
    int grid = sms < ntiles ? sms : ntiles;
    if (grid < 1) grid = 1;

    clifford_gate_kernel<<<grid, THREADS, SMEM_BYTES>>>(
        x, wp, bpr, wm, bmr, out, ntiles);
}